// round 1
// baseline (speedup 1.0000x reference)
#include <cuda_runtime.h>
#include <cstdint>

// ---------------------------------------------------------------------------
// SelfAttention (B=4, S=256, HID=1024, NH=8) -> effective attn seq 2048, HD=128
//
// Layout insight: (B,S,HID*NH) contiguous == (B, 2048, 8, 128) contiguous, so
// Q/K/V/context all stay in projection layout; attention addresses them with
// base offset b*2097152 + h*128 and row stride 1024.
//
// Pipeline (all tf32 mma.sync, fp32 accumulate):
//   1. Q = query @ Wq^T + bq   (M=1024, N=8192, K=1024)   x3 for K,V
//   2. S = Q @ K^T / 32        batched over 32 (b,h), M=N=2048, K=128
//   3. softmax rows (warp per row, in place)
//   4. Ctx = P @ V             batched, M=2048, N=128, K=2048  (B is k-major)
//   5. out = Ctx @ Wfc^T + bfc (M=1024, N=1024, K=8192)
// ---------------------------------------------------------------------------

// Scratch (device globals: allocation-free per harness rules)
__device__ float g_Q[8388608];      // (4, 2048, 8, 128)
__device__ float g_K[8388608];
__device__ float g_V[8388608];
__device__ float g_Ctx[8388608];
__device__ float g_S[134217728];    // (32, 2048, 2048) attention scores

__device__ __forceinline__ float f2tf32(float x) {
    float r;
    asm("cvt.rna.tf32.f32 %0, %1;" : "=f"(r) : "f"(x));
    return r;
}

__device__ __forceinline__ void mma_tf32(float* d, const uint32_t* a, const uint32_t* b) {
    asm volatile(
        "mma.sync.aligned.m16n8k8.row.col.f32.tf32.tf32.f32 "
        "{%0,%1,%2,%3}, {%4,%5,%6,%7}, {%8,%9}, {%0,%1,%2,%3};\n"
        : "+f"(d[0]), "+f"(d[1]), "+f"(d[2]), "+f"(d[3])
        : "r"(a[0]), "r"(a[1]), "r"(a[2]), "r"(a[3]),
          "r"(b[0]), "r"(b[1]));
}

// C[m,n] = scale * sum_k A[m,k] * B(k,n)  (+ bias[n])
// TRANS_B = true : B is row-major (n, k), ldb strides n rows   ("TN": both k-contig)
// TRANS_B = false: B is row-major (k, n), ldb strides k rows   ("NN")
// Batched via blockIdx.z: z0 = z>>3, z1 = z&7; base offsets z0*s?0 + z1*s?1.
template<bool TRANS_B>
__global__ void __launch_bounds__(256) gemm_tf32(
    const float* __restrict__ A, const float* __restrict__ Bm,
    float* __restrict__ C, const float* __restrict__ bias,
    int K, int lda, int ldb, int ldc,
    long long sA0, long long sA1, long long sB0, long long sB1,
    long long sC0, long long sC1, float scale)
{
    const int z = blockIdx.z, z0 = z >> 3, z1 = z & 7;
    A  += (long long)z0 * sA0 + (long long)z1 * sA1;
    Bm += (long long)z0 * sB0 + (long long)z1 * sB1;
    C  += (long long)z0 * sC0 + (long long)z1 * sC1;
    const int bm = blockIdx.y * 128;
    const int bn = blockIdx.x * 128;

    // As: [m(128)][k(32)] stride 36 (conflict-free frag loads: bank = 4g+t)
    // Bs TN: [n(128)][k(32)] stride 36 ; Bs NN: [k(32)][n(128)] stride 132
    __shared__ float As[128 * 36];
    __shared__ float Bs[128 * 36];

    const int t    = threadIdx.x;
    const int warp = t >> 5, lane = t & 31;
    const int wm = (warp >> 1) * 32;   // 4 warps along M
    const int wn = (warp & 1) * 64;    // 2 warps along N
    const int g  = lane >> 2, tg = lane & 3;

    float acc[2][8][4];
    #pragma unroll
    for (int mt = 0; mt < 2; mt++)
        #pragma unroll
        for (int nt = 0; nt < 8; nt++)
            #pragma unroll
            for (int r = 0; r < 4; r++) acc[mt][nt][r] = 0.0f;

    for (int kt = 0; kt < K; kt += 32) {
        // --- load A tile: 128 rows x 32 k, 4 float4 per thread ---
        #pragma unroll
        for (int i = 0; i < 4; i++) {
            int idx = t + i * 256;
            int row = idx >> 3;
            int c4  = (idx & 7) << 2;
            const float4 val = *(const float4*)(A + (long long)(bm + row) * lda + kt + c4);
            float* d = &As[row * 36 + c4];
            d[0] = f2tf32(val.x); d[1] = f2tf32(val.y);
            d[2] = f2tf32(val.z); d[3] = f2tf32(val.w);
        }
        // --- load B tile ---
        if (TRANS_B) {
            #pragma unroll
            for (int i = 0; i < 4; i++) {
                int idx = t + i * 256;
                int row = idx >> 3;           // n row
                int c4  = (idx & 7) << 2;
                const float4 val = *(const float4*)(Bm + (long long)(bn + row) * ldb + kt + c4);
                float* d = &Bs[row * 36 + c4];
                d[0] = f2tf32(val.x); d[1] = f2tf32(val.y);
                d[2] = f2tf32(val.z); d[3] = f2tf32(val.w);
            }
        } else {
            #pragma unroll
            for (int i = 0; i < 4; i++) {
                int idx = t + i * 256;
                int kr = idx >> 5;            // k row
                int c4 = (idx & 31) << 2;
                const float4 val = *(const float4*)(Bm + (long long)(kt + kr) * ldb + bn + c4);
                float* d = &Bs[kr * 132 + c4];
                d[0] = f2tf32(val.x); d[1] = f2tf32(val.y);
                d[2] = f2tf32(val.z); d[3] = f2tf32(val.w);
            }
        }
        __syncthreads();

        #pragma unroll
        for (int kk = 0; kk < 32; kk += 8) {
            uint32_t a[2][4];
            #pragma unroll
            for (int mt = 0; mt < 2; mt++) {
                const float* base = &As[(wm + mt * 16) * 36 + kk];
                a[mt][0] = __float_as_uint(base[(g    ) * 36 + tg    ]);
                a[mt][1] = __float_as_uint(base[(g + 8) * 36 + tg    ]);
                a[mt][2] = __float_as_uint(base[(g    ) * 36 + tg + 4]);
                a[mt][3] = __float_as_uint(base[(g + 8) * 36 + tg + 4]);
            }
            uint32_t b[8][2];
            #pragma unroll
            for (int nt = 0; nt < 8; nt++) {
                int n = wn + nt * 8 + g;
                if (TRANS_B) {
                    b[nt][0] = __float_as_uint(Bs[n * 36 + kk + tg    ]);
                    b[nt][1] = __float_as_uint(Bs[n * 36 + kk + tg + 4]);
                } else {
                    b[nt][0] = __float_as_uint(Bs[(kk + tg    ) * 132 + n]);
                    b[nt][1] = __float_as_uint(Bs[(kk + tg + 4) * 132 + n]);
                }
            }
            #pragma unroll
            for (int mt = 0; mt < 2; mt++)
                #pragma unroll
                for (int nt = 0; nt < 8; nt++)
                    mma_tf32(acc[mt][nt], a[mt], b[nt]);
        }
        __syncthreads();
    }

    // --- epilogue ---
    #pragma unroll
    for (int mt = 0; mt < 2; mt++) {
        #pragma unroll
        for (int nt = 0; nt < 8; nt++) {
            int m = bm + wm + mt * 16 + g;
            int n = bn + wn + nt * 8 + tg * 2;
            float bv0 = bias ? bias[n]     : 0.0f;
            float bv1 = bias ? bias[n + 1] : 0.0f;
            float2 r0, r1;
            r0.x = acc[mt][nt][0] * scale + bv0;
            r0.y = acc[mt][nt][1] * scale + bv1;
            r1.x = acc[mt][nt][2] * scale + bv0;
            r1.y = acc[mt][nt][3] * scale + bv1;
            *(float2*)(C + (long long)m * ldc + n)       = r0;
            *(float2*)(C + (long long)(m + 8) * ldc + n) = r1;
        }
    }
}

// In-place row softmax: one warp per 2048-float row, 65536 rows total.
__global__ void __launch_bounds__(256) softmax_rows(float* __restrict__ S)
{
    const long long row = (long long)blockIdx.x * 8 + (threadIdx.x >> 5);
    const int lane = threadIdx.x & 31;
    float4* r = (float4*)(S + row * 2048);

    float4 v[16];
    float mx = -3.4e38f;
    #pragma unroll
    for (int i = 0; i < 16; i++) {
        v[i] = r[lane + i * 32];
        mx = fmaxf(mx, fmaxf(fmaxf(v[i].x, v[i].y), fmaxf(v[i].z, v[i].w)));
    }
    #pragma unroll
    for (int off = 16; off > 0; off >>= 1)
        mx = fmaxf(mx, __shfl_xor_sync(0xFFFFFFFFu, mx, off));

    float sum = 0.0f;
    #pragma unroll
    for (int i = 0; i < 16; i++) {
        v[i].x = __expf(v[i].x - mx);
        v[i].y = __expf(v[i].y - mx);
        v[i].z = __expf(v[i].z - mx);
        v[i].w = __expf(v[i].w - mx);
        sum += (v[i].x + v[i].y) + (v[i].z + v[i].w);
    }
    #pragma unroll
    for (int off = 16; off > 0; off >>= 1)
        sum += __shfl_xor_sync(0xFFFFFFFFu, sum, off);

    const float inv = 1.0f / sum;
    #pragma unroll
    for (int i = 0; i < 16; i++) {
        v[i].x *= inv; v[i].y *= inv; v[i].z *= inv; v[i].w *= inv;
        r[lane + i * 32] = v[i];
    }
}

extern "C" void kernel_launch(void* const* d_in, const int* in_sizes, int n_in,
                              void* d_out, int out_size)
{
    (void)in_sizes; (void)n_in; (void)out_size;
    const float* query = (const float*)d_in[0];
    const float* key_  = (const float*)d_in[1];
    const float* value = (const float*)d_in[2];
    const float* Wq    = (const float*)d_in[3];
    const float* bq    = (const float*)d_in[4];
    const float* Wk    = (const float*)d_in[5];
    const float* bk    = (const float*)d_in[6];
    const float* Wv    = (const float*)d_in[7];
    const float* bv    = (const float*)d_in[8];
    const float* Wfc   = (const float*)d_in[9];
    const float* bfc   = (const float*)d_in[10];
    float* out = (float*)d_out;

    float *Q, *K, *V, *Ctx, *S;
    cudaGetSymbolAddress((void**)&Q,   g_Q);
    cudaGetSymbolAddress((void**)&K,   g_K);
    cudaGetSymbolAddress((void**)&V,   g_V);
    cudaGetSymbolAddress((void**)&Ctx, g_Ctx);
    cudaGetSymbolAddress((void**)&S,   g_S);

    const dim3 blk(256);

    // 1) Projections: M=1024, N=8192, K=1024 (TN, bias)
    gemm_tf32<true><<<dim3(64, 8, 1), blk>>>(query, Wq, Q, bq,
        1024, 1024, 1024, 8192, 0, 0, 0, 0, 0, 0, 1.0f);
    gemm_tf32<true><<<dim3(64, 8, 1), blk>>>(key_,  Wk, K, bk,
        1024, 1024, 1024, 8192, 0, 0, 0, 0, 0, 0, 1.0f);
    gemm_tf32<true><<<dim3(64, 8, 1), blk>>>(value, Wv, V, bv,
        1024, 1024, 1024, 8192, 0, 0, 0, 0, 0, 0, 1.0f);

    // 2) Scores: per (b,h): S = Q @ K^T / 32 ; M=N=2048, K=128
    //    A base = b*2097152 + h*128 (lda=1024); C base = bh*4194304 (ldc=2048)
    gemm_tf32<true><<<dim3(16, 16, 32), blk>>>(Q, K, S, nullptr,
        128, 1024, 1024, 2048,
        2097152LL, 128LL, 2097152LL, 128LL, 33554432LL, 4194304LL, 0.03125f);

    // 3) Softmax over each of 65536 rows of length 2048
    softmax_rows<<<8192, blk>>>(S);

    // 4) Ctx = P @ V : per (b,h): M=2048, N=128, K=2048 (NN: V is k-major)
    gemm_tf32<false><<<dim3(1, 16, 32), blk>>>(S, V, Ctx, nullptr,
        2048, 2048, 1024, 1024,
        33554432LL, 4194304LL, 2097152LL, 128LL, 2097152LL, 128LL, 1.0f);

    // 5) out = Ctx @ Wfc^T + bfc : M=1024, N=1024, K=8192 (TN)
    gemm_tf32<true><<<dim3(8, 8, 1), blk>>>(Ctx, Wfc, out, bfc,
        8192, 8192, 8192, 1024, 0, 0, 0, 0, 0, 0, 1.0f);
}